// round 1
// baseline (speedup 1.0000x reference)
#include <cuda_runtime.h>
#include <cstdint>

#define BB 8
#define CC 64
#define NTOK 4096
#define BN_EPS 1e-5f

// Scratch (allocation-free rule: __device__ globals)
__device__ float g_z[BB * CC * NTOK];        // 8 MB conv output
__device__ float g_partV[BB * CC * 16];      // per-(b,o) per-chunk sum z
__device__ float g_partQ[BB * CC * 16];      // per-(b,o) per-chunk sum z^2
__device__ float g_alpha[BB * CC];
__device__ float g_bet[BB * CC];

// ---- packed f32x2 helpers (B300: doubles fp32 throughput; PTX-only) ----
__device__ __forceinline__ unsigned long long ffma2(unsigned long long a,
                                                    unsigned long long b,
                                                    unsigned long long c) {
    unsigned long long d;
    asm("fma.rn.f32x2 %0, %1, %2, %3;" : "=l"(d) : "l"(a), "l"(b), "l"(c));
    return d;
}
__device__ __forceinline__ unsigned long long fadd2(unsigned long long a,
                                                    unsigned long long b) {
    unsigned long long d;
    asm("add.rn.f32x2 %0, %1, %2;" : "=l"(d) : "l"(a), "l"(b));
    return d;
}
__device__ __forceinline__ unsigned long long packpair(float w) {
    unsigned long long p;
    asm("mov.b64 %0, {%1, %2};" : "=l"(p) : "f"(w), "f"(w));
    return p;
}
__device__ __forceinline__ void unpack2(unsigned long long v, float& lo, float& hi) {
    asm("mov.b64 {%0, %1}, %2;" : "=f"(lo), "=f"(hi) : "l"(v));
}

// ============================================================================
// K1: z = W @ x  (64x64 channel matmul per position), + per-block Σz, Σz²
// grid (16 n-chunks, 8 batches), 128 threads, 2 n-positions per thread (f32x2)
// dyn smem: Wp pairs 32768 B + part 64*129*8 = 66048 B -> 98816 B
// ============================================================================
#define K1_SMEM (32768 + 64 * 129 * 8)

__global__ __launch_bounds__(128) void k_conv(const float* __restrict__ x,
                                              const float* __restrict__ convw) {
    extern __shared__ char smem[];
    unsigned long long* Wp = reinterpret_cast<unsigned long long*>(smem);      // [64*64] pairs
    float2* part = reinterpret_cast<float2*>(smem + 32768);                    // [64][129]

    const int tid = threadIdx.x;
    const int chunk = blockIdx.x;      // 0..15
    const int b = blockIdx.y;          // 0..7

    // Stage conv_w as duplicated pairs {w,w} so LDS.128 feeds 2x FFMA2
    for (int i = tid; i < CC * CC; i += 128) {
        Wp[i] = packpair(convw[i]);
    }

    const int n = chunk * 256 + 2 * tid;       // 8B-aligned (n even)
    const float* xb = x + (size_t)b * CC * NTOK + n;

    // 64 channel values for 2 positions, packed f32x2, in registers
    unsigned long long xr[CC];
#pragma unroll
    for (int c = 0; c < CC; c++) {
        xr[c] = *reinterpret_cast<const unsigned long long*>(xb + (size_t)c * NTOK);
    }
    __syncthreads();

    float* zb = g_z + (size_t)b * CC * NTOK + n;

    for (int o = 0; o < CC; o++) {
        const ulonglong2* wrow = reinterpret_cast<const ulonglong2*>(Wp + o * CC);
        unsigned long long a0 = 0ull, a1 = 0ull, a2 = 0ull, a3 = 0ull;  // +0.f pairs
#pragma unroll
        for (int k = 0; k < 16; k++) {
            ulonglong2 w01 = wrow[2 * k];
            ulonglong2 w23 = wrow[2 * k + 1];
            a0 = ffma2(w01.x, xr[4 * k + 0], a0);
            a1 = ffma2(w01.y, xr[4 * k + 1], a1);
            a2 = ffma2(w23.x, xr[4 * k + 2], a2);
            a3 = ffma2(w23.y, xr[4 * k + 3], a3);
        }
        unsigned long long s01 = fadd2(fadd2(a0, a1), fadd2(a2, a3));
        // store both lanes (lo = n, hi = n+1; little-endian pack matches memory order)
        *reinterpret_cast<unsigned long long*>(zb + (size_t)o * NTOK) = s01;

        float lo, hi;
        unpack2(s01, lo, hi);
        part[o * 129 + tid] = make_float2(lo + hi, lo * lo + hi * hi);
    }
    __syncthreads();

    // transpose-reduce: thread t (<64) sums row o=t across 128 threads
    if (tid < CC) {
        float v = 0.f, q = 0.f;
        for (int t = 0; t < 128; t++) {
            float2 p = part[tid * 129 + t];
            v += p.x;
            q += p.y;
        }
        const int j = (b * CC + tid) * 16 + chunk;
        g_partV[j] = v;
        g_partQ[j] = q;
    }
}

// ============================================================================
// K2: finalize — s_b from w, Z/Q from partials, BN stats, per-(b,o) affine
// single block, 256 threads
// ============================================================================
__global__ __launch_bounds__(256) void k_fin(const float* __restrict__ w,
                                             const float* __restrict__ convb,
                                             const float* __restrict__ gamma,
                                             const float* __restrict__ beta) {
    __shared__ float s_sh[BB];
    __shared__ float g_sh[BB * CC];
    __shared__ float cM[BB * CC];
    __shared__ float cE[BB * CC];
    __shared__ float mean_sh[CC];
    __shared__ float scale_sh[CC];

    const int tid = threadIdx.x;
    const int warp = tid >> 5, lane = tid & 31;

    // s_b = sum_n relu(tanh(w))^2 : one warp per batch
    if (warp < BB) {
        const float* wb = w + warp * NTOK;
        float s = 0.f;
        for (int i = lane; i < NTOK; i += 32) {
            float t = tanhf(wb[i]);
            t = fmaxf(t, 0.f);
            s += t * t;
        }
#pragma unroll
        for (int off = 16; off; off >>= 1) s += __shfl_xor_sync(0xffffffffu, s, off);
        if (lane == 0) s_sh[warp] = s;
    }
    __syncthreads();

    // per-(b,o): Z, Q, g, and BN-stat contributions
    for (int j = tid; j < BB * CC; j += 256) {
        const int b = j >> 6, o = j & 63;
        float Z = 0.f, Q = 0.f;
#pragma unroll
        for (int k = 0; k < 16; k++) {
            Z += g_partV[j * 16 + k];
            Q += g_partQ[j * 16 + k];
        }
        const float s = s_sh[b];
        const float d = s * (float)NTOK + 1.0f;
        const float inv = 1.0f / d;
        const float g = s * Z * inv + convb[o];
        g_sh[j] = g;
        cM[j] = Z * inv + (float)NTOK * g;                              // Σ_n y
        cE[j] = Q * inv * inv + 2.0f * g * Z * inv + (float)NTOK * g * g;  // Σ_n y²
    }
    __syncthreads();

    if (tid < CC) {
        float m = 0.f, e = 0.f;
#pragma unroll
        for (int b = 0; b < BB; b++) {
            m += cM[b * CC + tid];
            e += cE[b * CC + tid];
        }
        const float invBN = 1.0f / (float)(BB * NTOK);
        m *= invBN;
        e *= invBN;
        const float var = e - m * m;
        mean_sh[tid] = m;
        scale_sh[tid] = gamma[tid] * rsqrtf(var + BN_EPS);
    }
    __syncthreads();

    for (int j = tid; j < BB * CC; j += 256) {
        const int b = j >> 6, o = j & 63;
        const float s = s_sh[b];
        const float d = s * (float)NTOK + 1.0f;
        const float sc = scale_sh[o];
        g_alpha[j] = sc / d;
        g_bet[j] = sc * (g_sh[j] - mean_sh[o]) + beta[o];
    }
}

// ============================================================================
// K3: out = relu(alpha[b,o] * z + bet[b,o])  — streaming, float4
// 512 blocks (one per (b,o) row of 4096), 256 threads
// ============================================================================
__global__ __launch_bounds__(256) void k_apply(float* __restrict__ out) {
    const int bo = blockIdx.x;  // 0..511
    const float a = g_alpha[bo];
    const float c = g_bet[bo];
    const float4* z4 = reinterpret_cast<const float4*>(g_z + (size_t)bo * NTOK);
    float4* o4 = reinterpret_cast<float4*>(out + (size_t)bo * NTOK);
    const int tid = threadIdx.x;
#pragma unroll
    for (int it = 0; it < 4; it++) {
        const int i = it * 256 + tid;
        float4 z = z4[i];
        float4 r;
        r.x = fmaxf(fmaf(a, z.x, c), 0.f);
        r.y = fmaxf(fmaf(a, z.y, c), 0.f);
        r.z = fmaxf(fmaf(a, z.z, c), 0.f);
        r.w = fmaxf(fmaf(a, z.w, c), 0.f);
        o4[i] = r;
    }
}

// ============================================================================
extern "C" void kernel_launch(void* const* d_in, const int* in_sizes, int n_in,
                              void* d_out, int out_size) {
    const float* x     = (const float*)d_in[0];  // [8,64,4096,1]
    const float* w     = (const float*)d_in[1];  // [8,4096]
    const float* convw = (const float*)d_in[2];  // [64,64,1,1]
    const float* convb = (const float*)d_in[3];  // [64]
    const float* gamma = (const float*)d_in[4];  // [64]
    const float* beta  = (const float*)d_in[5];  // [64]
    float* out = (float*)d_out;                  // [8,64,4096,1]
    (void)in_sizes; (void)n_in; (void)out_size;

    // >48KB dynamic smem needs opt-in (non-enqueueing call; capture-safe)
    cudaFuncSetAttribute(k_conv, cudaFuncAttributeMaxDynamicSharedMemorySize, K1_SMEM);

    dim3 g1(16, BB);
    k_conv<<<g1, 128, K1_SMEM>>>(x, convw);
    k_fin<<<1, 256>>>(w, convb, gamma, beta);
    k_apply<<<BB * CC, 256>>>(out);
}

// round 12
// speedup vs baseline: 1.4891x; 1.4891x over previous
#include <cuda_runtime.h>
#include <cstdint>

#define BB 8
#define CC 64
#define NTOK 4096
#define BN_EPS 1e-5f

typedef unsigned long long ull;

// Scratch (allocation-free rule: __device__ globals)
__device__ float g_z[BB * CC * NTOK];        // 8 MB conv output (L2-resident)
__device__ float g_partV[CC * BB * 16];      // [o][b][chunk] sum z
__device__ float g_partQ[CC * BB * 16];      // [o][b][chunk] sum z^2
__device__ float g_s[BB];                    // s_b

// ---- packed f32x2 helpers (B300: doubles fp32 throughput; PTX-only) ----
__device__ __forceinline__ ull ffma2(ull a, ull b, ull c) {
    ull d;
    asm("fma.rn.f32x2 %0, %1, %2, %3;" : "=l"(d) : "l"(a), "l"(b), "l"(c));
    return d;
}
__device__ __forceinline__ ull fadd2(ull a, ull b) {
    ull d;
    asm("add.rn.f32x2 %0, %1, %2;" : "=l"(d) : "l"(a), "l"(b));
    return d;
}
__device__ __forceinline__ ull packpair(float w) {
    ull p;
    asm("mov.b64 %0, {%1, %2};" : "=l"(p) : "f"(w), "f"(w));
    return p;
}
__device__ __forceinline__ void unpack2(ull v, float& lo, float& hi) {
    asm("mov.b64 {%0, %1}, %2;" : "=f"(lo), "=f"(hi) : "l"(v));
}

// ============================================================================
// K1: z = W @ x per position + per-block Σz, Σz² ; chunk-0 blocks also do s_b
// grid (16 chunks, 8 b), 512 threads:
//   p  = tid & 127  -> n-pair (2 positions via f32x2)
//   h  = (tid>>7)&1 -> o-half  [h*32, h*32+32)
//   kh = tid>>8     -> k-half  channels [kh*32, kh*32+32)
// 1 block/SM, 16 warps = 4 warps/SMSP.
// ============================================================================
#define WP_OFF    0                       // 4096 ull  = 32768 B  (conv_w pairs)
#define PART_OFF  32768                   // [16][2][128] ull = 32768 B
#define STATS_OFF 65536                   // [64][130] float2 = 66560 B (padded)
#define RED_OFF   (65536 + 66560)         // 16 floats
#define K1_SMEM   (RED_OFF + 64)

__global__ __launch_bounds__(512) void k_conv(const float* __restrict__ x,
                                              const float* __restrict__ convw,
                                              const float* __restrict__ w) {
    extern __shared__ char smem[];
    ull*    Wp    = reinterpret_cast<ull*>(smem + WP_OFF);      // [64][64] pairs
    ull*    part  = reinterpret_cast<ull*>(smem + PART_OFF);    // [(h*8+i)][kh][128]
    float2* stats = reinterpret_cast<float2*>(smem + STATS_OFF);// [64][130]
    float*  red   = reinterpret_cast<float*>(smem + RED_OFF);

    const int tid = threadIdx.x;
    const int p   = tid & 127;
    const int h   = (tid >> 7) & 1;
    const int kh  = tid >> 8;
    const int chunk = blockIdx.x;
    const int b     = blockIdx.y;

    // Stage conv_w as duplicated pairs {w,w}
    for (int i = tid; i < CC * CC; i += 512) Wp[i] = packpair(convw[i]);

    const int n = chunk * 256 + 2 * p;
    const float* xb = x + (size_t)b * CC * NTOK + (size_t)(kh * 32) * NTOK + n;

    // 32 channels x 2 positions, packed f32x2, register-resident
    ull xr[32];
#pragma unroll
    for (int c = 0; c < 32; c++) {
        xr[c] = *reinterpret_cast<const ull*>(xb + (size_t)c * NTOK);
    }
    __syncthreads();

    float* zb = g_z + (size_t)b * CC * NTOK;

    for (int og = 0; og < 4; og++) {
#pragma unroll
        for (int i = 0; i < 8; i++) {
            const int o = h * 32 + og * 8 + i;
            const ulonglong2* wrow =
                reinterpret_cast<const ulonglong2*>(Wp + o * CC + kh * 32);
            ull a0 = 0ull, a1 = 0ull, a2 = 0ull, a3 = 0ull;
#pragma unroll
            for (int k = 0; k < 8; k++) {
                ulonglong2 w01 = wrow[2 * k];
                ulonglong2 w23 = wrow[2 * k + 1];
                a0 = ffma2(w01.x, xr[4 * k + 0], a0);
                a1 = ffma2(w01.y, xr[4 * k + 1], a1);
                a2 = ffma2(w23.x, xr[4 * k + 2], a2);
                a3 = ffma2(w23.y, xr[4 * k + 3], a3);
            }
            part[(h * 8 + i) * 256 + kh * 128 + p] =
                fadd2(fadd2(a0, a1), fadd2(a2, a3));
        }
        __syncthreads();
        if (kh == 0) {
#pragma unroll
            for (int i = 0; i < 8; i++) {
                const int o = h * 32 + og * 8 + i;
                const int slot = (h * 8 + i) * 256 + p;
                ull z2 = fadd2(part[slot], part[slot + 128]);
                *reinterpret_cast<ull*>(zb + (size_t)o * NTOK + n) = z2;
                float lo, hi;
                unpack2(z2, lo, hi);
                stats[o * 130 + p] = make_float2(lo + hi, lo * lo + hi * hi);
            }
        }
        __syncthreads();
    }

    // reduce stats over the 128 p-slots: 2 threads per o
    if (tid < 128) {
        const int o = tid >> 1, half = tid & 1;
        float v = 0.f, q = 0.f;
        for (int j = half * 64; j < half * 64 + 64; j++) {
            float2 s2 = stats[o * 130 + j];
            v += s2.x;
            q += s2.y;
        }
        v += __shfl_down_sync(0xffffffffu, v, 1);
        q += __shfl_down_sync(0xffffffffu, q, 1);
        if (half == 0) {
            const int idx = o * 128 + b * 16 + chunk;  // [o][b][chunk]
            g_partV[idx] = v;
            g_partQ[idx] = q;
        }
    }

    // chunk-0 blocks: s_b = sum_n relu(tanh(w))^2
    if (chunk == 0) {
        const float* wb = w + b * NTOK;
        float s = 0.f;
        for (int i = tid; i < NTOK; i += 512) {
            float t = tanhf(wb[i]);
            t = fmaxf(t, 0.f);
            s += t * t;
        }
#pragma unroll
        for (int off = 16; off; off >>= 1) s += __shfl_xor_sync(0xffffffffu, s, off);
        if ((tid & 31) == 0) red[tid >> 5] = s;
        __syncthreads();
        if (tid < 16) {
            s = red[tid];
#pragma unroll
            for (int off = 8; off; off >>= 1) s += __shfl_xor_sync(0x0000ffffu, s, off);
            if (tid == 0) g_s[b] = s;
        }
    }
}

// ============================================================================
// K2: per-block finalize (alpha,beta for own (b,o)) + streamed affine/relu
// 512 blocks (one per (b,o) row of 4096), 256 threads
// ============================================================================
__global__ __launch_bounds__(256) void k_apply(float* __restrict__ out,
                                               const float* __restrict__ convb,
                                               const float* __restrict__ gamma,
                                               const float* __restrict__ beta) {
    __shared__ float2 ab_sh;
    const int bo = blockIdx.x;  // 0..511
    const int b = bo >> 6, o = bo & 63;

    if (threadIdx.x < 32) {
        const int lane = threadIdx.x;
        float cM = 0.f, cE = 0.f, g = 0.f, inv = 0.f;
        if (lane < 8) {
            float Z = 0.f, Q = 0.f;
#pragma unroll
            for (int k = 0; k < 16; k++) {
                Z += g_partV[o * 128 + lane * 16 + k];
                Q += g_partQ[o * 128 + lane * 16 + k];
            }
            const float s = g_s[lane];
            const float d = fmaf(s, (float)NTOK, 1.0f);
            inv = 1.0f / d;
            g = s * Z * inv + convb[o];
            cM = Z * inv + (float)NTOK * g;
            cE = Q * inv * inv + 2.0f * g * Z * inv + (float)NTOK * g * g;
        }
        float m = cM, e = cE;
#pragma unroll
        for (int off = 16; off; off >>= 1) {
            m += __shfl_xor_sync(0xffffffffu, m, off);
            e += __shfl_xor_sync(0xffffffffu, e, off);
        }
        const float invBN = 1.0f / (float)(BB * NTOK);
        m *= invBN;
        e *= invBN;
        const float var = e - m * m;
        const float scale = gamma[o] * rsqrtf(var + BN_EPS);
        if (lane == b) {
            ab_sh = make_float2(scale * inv, scale * (g - m) + beta[o]);
        }
    }
    __syncthreads();

    const float a = ab_sh.x;
    const float c = ab_sh.y;
    const float4* z4 = reinterpret_cast<const float4*>(g_z + (size_t)bo * NTOK);
    float4* o4 = reinterpret_cast<float4*>(out + (size_t)bo * NTOK);
    const int tid = threadIdx.x;
#pragma unroll
    for (int it = 0; it < 4; it++) {
        const int i = it * 256 + tid;
        float4 z = z4[i];
        float4 r;
        r.x = fmaxf(fmaf(a, z.x, c), 0.f);
        r.y = fmaxf(fmaf(a, z.y, c), 0.f);
        r.z = fmaxf(fmaf(a, z.z, c), 0.f);
        r.w = fmaxf(fmaf(a, z.w, c), 0.f);
        o4[i] = r;
    }
}

// ============================================================================
extern "C" void kernel_launch(void* const* d_in, const int* in_sizes, int n_in,
                              void* d_out, int out_size) {
    const float* x     = (const float*)d_in[0];  // [8,64,4096,1]
    const float* w     = (const float*)d_in[1];  // [8,4096]
    const float* convw = (const float*)d_in[2];  // [64,64,1,1]
    const float* convb = (const float*)d_in[3];  // [64]
    const float* gamma = (const float*)d_in[4];  // [64]
    const float* beta  = (const float*)d_in[5];  // [64]
    float* out = (float*)d_out;                  // [8,64,4096,1]
    (void)in_sizes; (void)n_in; (void)out_size;

    cudaFuncSetAttribute(k_conv, cudaFuncAttributeMaxDynamicSharedMemorySize, K1_SMEM);

    dim3 g1(16, BB);
    k_conv<<<g1, 512, K1_SMEM>>>(x, convw, w);
    k_apply<<<BB * CC, 256>>>(out, convb, gamma, beta);
}